// round 12
// baseline (speedup 1.0000x reference)
#include <cuda_runtime.h>
#include <math.h>
#include <stdint.h>

#define BB 8
#define CC 80
#define K_OUT 100
#define SEL 1000
#define NSEL 3000          // 3 levels x 1000 (level2 has 1024 > NMS_PRE=1000)
#define TOPM 256           // scan depth (scan consumes ~110; >2x margin)
#define CAP 512            // superset capacity for nms_sort
#define FCAP 256           // superset capacity for k_final
#define N0 16384
#define N1 4096
#define N2 1024
#define NTOT (N0 + N1 + N2)   // 21504
#define W0 128
#define W1 64
#define W2 32
#define IOU_THR 0.5f
#define BOX_SCORE 0.3f
#define IMGSZ 1024.0f
#define S03 0xBE99999Au    // sortable-uint encoding of 0.3f
#define PIDX(i) ((i) + ((i) >> 4))   // bank-conflict padding
#define MLR 128            // rows per k_ml tile
#define MLTILES (BB * NTOT / MLR)    // 1344
#define MLGRID 448                   // resident blocks (3 tiles each)

typedef unsigned long long u64;

// ------------------------- device scratch (no allocs allowed) ---------------
__device__ float  g_ml[BB * NTOT];            // max class logit per anchor
__device__ int    g_idx[BB * NSEL];           // selected anchor (level-local id)
__device__ float4 g_boxes[BB * NSEL];         // x1,y1,x2,y2
__device__ float  g_scores[BB * CC * NSEL];   // class-major sigmoid scores
__device__ float4 g_selb[BB * CC * K_OUT];    // NMS-selected boxes
__device__ float  g_sels[BB * CC * K_OUT];    // NMS-selected scores

__device__ __forceinline__ unsigned f2sort(float x) {
    unsigned u = __float_as_uint(x);
    return (u & 0x80000000u) ? ~u : (u | 0x80000000u);
}

// ------------------------- K1: max class logit, persistent grid-stride ------
__global__ void __launch_bounds__(512) k_ml(const float* __restrict__ c0,
                                            const float* __restrict__ c1,
                                            const float* __restrict__ c2) {
    __shared__ float pm[MLR * 20];   // 2560 per-float4 maxes
    int tid = threadIdx.x;
    for (int t = blockIdx.x; t < MLTILES; t += MLGRID) {
        const float4* src;
        int R0, shift, mask, off;
        if (t < BB * N0 / MLR) {
            src = (const float4*)c0; R0 = t * MLR;
            shift = 14; mask = N0 - 1; off = 0;
        } else if (t < BB * (N0 + N1) / MLR) {
            src = (const float4*)c1; R0 = (t - BB * N0 / MLR) * MLR;
            shift = 12; mask = N1 - 1; off = N0;
        } else {
            src = (const float4*)c2; R0 = (t - BB * (N0 + N1) / MLR) * MLR;
            shift = 10; mask = N2 - 1; off = N0 + N1;
        }
        src += (size_t)R0 * 20;
#pragma unroll
        for (int p = 0; p < 5; p++) {
            int f = tid + (p << 9);      // 0..2559
            float4 v = src[f];
            pm[f] = fmaxf(fmaxf(v.x, v.y), fmaxf(v.z, v.w));
        }
        __syncthreads();
        if (tid < MLR) {
            float m = -INFINITY;
#pragma unroll
            for (int j = 0; j < 20; j++) m = fmaxf(m, pm[tid * 20 + j]);
            int R = R0 + tid;
            g_ml[(R >> shift) * NTOT + off + (R & mask)] = m;
        }
        __syncthreads();
    }
}

// ------------------------- K2: exact top-1000 per (image, level) ------------
__global__ void k_select() {
    int blk = blockIdx.x;
    int b = blk / 3, lvl = blk % 3;
    int N, off;
    if (lvl == 0)      { N = N0; off = 0; }
    else if (lvl == 1) { N = N1; off = N0; }
    else               { N = N2; off = N0 + N1; }
    int nwords = N >> 10;   // 16 / 4 / 1 per thread (1024 threads)

    int tid = threadIdx.x;
    int wid = tid >> 5, lane = tid & 31;
    const float* src = g_ml + b * NTOT + off;
    unsigned key[16];
    for (int r = 0; r < nwords; r++) key[r] = f2sort(src[tid + (r << 10)]);

    __shared__ int s_w[2][32];
    unsigned ans = 0;
    int tot = 0;
    for (int bit = 31; bit >= 0; --bit) {
        unsigned cand = ans | (1u << bit);
        int lc = 0;
        for (int r = 0; r < nwords; r++) lc += (key[r] >= cand);
        lc = __reduce_add_sync(0xffffffffu, lc);
        if (lane == 0) s_w[bit & 1][wid] = lc;
        __syncthreads();
        tot = __reduce_add_sync(0xffffffffu, s_w[bit & 1][lane]);
        if (tot >= SEL) ans = cand;
    }
    {
        int lc = 0;
        for (int r = 0; r < nwords; r++) lc += (key[r] > ans);
        lc = __reduce_add_sync(0xffffffffu, lc);
        if (lane == 0) s_w[0][wid] = lc;
        __syncthreads();
        tot = __reduce_add_sync(0xffffffffu, s_w[0][lane]);
    }
    int cntG = tot;

    __shared__ int gp, ep;
    if (tid == 0) { gp = 0; ep = 0; }
    __syncthreads();
    int* out = g_idx + b * NSEL + lvl * SEL;
    for (int r = 0; r < nwords; r++) {
        unsigned u = key[r];
        int i = tid + (r << 10);
        if (u > ans)       { int p = atomicAdd(&gp, 1); out[p] = i; }
        else if (u == ans) { int e = atomicAdd(&ep, 1); int p = cntG + e; if (p < SEL) out[p] = i; }
    }
}

// ------------------------- K3: fused decode (boxes + transposed scores) -----
__device__ __forceinline__ void anchor_of(int b, int n, int& lvl, int& a) {
    a = g_idx[b * NSEL + n];
    lvl = (n < SEL) ? 0 : (n < 2 * SEL ? 1 : 2);
}

#define TTILE 32
__global__ void k_decode(const float* __restrict__ c0,
                         const float* __restrict__ c1,
                         const float* __restrict__ c2,
                         const float* __restrict__ p0,
                         const float* __restrict__ p1,
                         const float* __restrict__ p2) {
    __shared__ float tile[TTILE][CC + 1];
    int blk = blockIdx.x;
    int ntiles = (NSEL + TTILE - 1) / TTILE;
    int b = blk / ntiles;
    int base = (blk % ntiles) * TTILE;
    int tid = threadIdx.x;

    // warp 0: boxes for the block's 32 anchors (one per lane)
    if (tid < 32) {
        int n = base + tid;
        if (n < NSEL) {
            int lvl, a;
            anchor_of(b, n, lvl, a);
            const float* bp; int NL, Wd; float stride;
            if (lvl == 0)      { bp = p0; NL = N0; Wd = W0; stride = 8.f; }
            else if (lvl == 1) { bp = p1; NL = N1; Wd = W1; stride = 16.f; }
            else               { bp = p2; NL = N2; Wd = W2; stride = 32.f; }
            const float4* row4 = reinterpret_cast<const float4*>(bp + ((size_t)b * NL + a) * 32);
            float d[4];
#pragma unroll
            for (int s = 0; s < 4; s++) {
                float4 q0 = row4[s * 2], q1 = row4[s * 2 + 1];
                float v[8] = {q0.x, q0.y, q0.z, q0.w, q1.x, q1.y, q1.z, q1.w};
                float m = -INFINITY;
#pragma unroll
                for (int j = 0; j < 8; j++) m = fmaxf(m, v[j]);
                float se = 0.f, sw = 0.f;
#pragma unroll
                for (int j = 0; j < 8; j++) { float e = expf(v[j] - m); se += e; sw += e * (float)j; }
                d[s] = sw / se * stride;
            }
            int h = a / Wd, w = a % Wd;
            float py = (h + 0.5f) * stride, px = (w + 0.5f) * stride;
            float y1 = fminf(fmaxf(py - d[0], 0.f), IMGSZ);
            float x1 = fminf(fmaxf(px - d[1], 0.f), IMGSZ);
            float y2 = fminf(fmaxf(py + d[2], 0.f), IMGSZ);
            float x2 = fminf(fmaxf(px + d[3], 0.f), IMGSZ);
            g_boxes[b * NSEL + n] = make_float4(x1, y1, x2, y2);
        }
    }

    // all threads: gather 32x80 score tile (coalesced rows), transpose-store
    for (int idx = tid; idx < TTILE * CC; idx += blockDim.x) {
        int nl = idx / CC, c = idx % CC;
        int n = base + nl;
        float x = 0.f;
        if (n < NSEL) {
            int lvl, a;
            anchor_of(b, n, lvl, a);
            const float* cls; int NL;
            if (lvl == 0)      { cls = c0; NL = N0; }
            else if (lvl == 1) { cls = c1; NL = N1; }
            else               { cls = c2; NL = N2; }
            x = cls[((size_t)b * NL + a) * CC + c];
        }
        tile[nl][c] = 1.f / (1.f + expf(-x));
    }
    __syncthreads();
    for (int idx = tid; idx < TTILE * CC; idx += blockDim.x) {
        int c = idx / TTILE, nl = idx % TTILE;
        int n = base + nl;
        if (n < NSEL)
            g_scores[((size_t)b * CC + c) * NSEL + n] = tile[nl][c];
    }
}

// ------------------------- K4: fused select+sort (x4) then 4-warp scan ------
// Block handles 4 consecutive (b,c): sorts each top-256 into smem, then each
// warp runs the sorted greedy scan for one class.
__global__ void __launch_bounds__(128) k_nms() {
    int bc0 = blockIdx.x * 4;
    int tid = threadIdx.x;
    int lane = tid & 31, wid = tid >> 5;

    __shared__ int s_w[2][4];
    __shared__ int s_cnt;
    __shared__ u64 sbuf[CAP + CAP / 16];
    __shared__ u64 tops[4][TOPM];

    for (int it = 0; it < 4; it++) {
        int bc = bc0 + it;
        // 24 keys via 6 float4 loads (750 float4 over 128 threads)
        unsigned key[24];
        const float4* sc4 = reinterpret_cast<const float4*>(g_scores + (size_t)bc * NSEL);
#pragma unroll
        for (int p = 0; p < 6; p++) {
            int q = tid + (p << 7);
            if (q < NSEL / 4) {
                float4 f = sc4[q];
                key[p * 4 + 0] = f2sort(f.x);
                key[p * 4 + 1] = f2sort(f.y);
                key[p * 4 + 2] = f2sort(f.z);
                key[p * 4 + 3] = f2sort(f.w);
            } else {
                key[p * 4 + 0] = key[p * 4 + 1] = key[p * 4 + 2] = key[p * 4 + 3] = 0u;
            }
        }

        // windowed radix search: stop once count(>=ans) in [TOPM, CAP]
        unsigned ans = 0;
        int cur = NSEL;
        for (int bit = 31; bit >= 0; --bit) {
            if (cur <= CAP) break;           // uniform decision
            unsigned cand = ans | (1u << bit);
            int lc = 0;
#pragma unroll
            for (int r = 0; r < 24; r++) lc += (key[r] >= cand);
            lc = __reduce_add_sync(0xffffffffu, lc);
            if (lane == 0) s_w[bit & 1][wid] = lc;
            __syncthreads();
            int tot = s_w[bit & 1][0] + s_w[bit & 1][1] + s_w[bit & 1][2] + s_w[bit & 1][3];
            if (tot >= TOPM) { ans = cand; cur = tot; }
        }

        // warp-aggregated compaction (order irrelevant: sort uses full key)
        if (tid == 0) s_cnt = 0;
        for (int i = tid; i < CAP + CAP / 16; i += 128) sbuf[i] = 0ULL;
        __syncthreads();
#pragma unroll
        for (int r = 0; r < 24; r++) {
            bool pred = (key[r] >= ans) && key[r];
            unsigned m = __ballot_sync(0xffffffffu, pred);
            int cnt = __popc(m);
            int base = 0;
            if (lane == 0 && cnt) base = atomicAdd(&s_cnt, cnt);
            base = __shfl_sync(0xffffffffu, base, 0);
            if (pred) {
                int pos = base + __popc(m & ((1u << lane) - 1u));
                int i = (tid + ((r >> 2) << 7)) * 4 + (r & 3);
                if (pos < CAP) sbuf[PIDX(pos)] = ((u64)key[r] << 32) | (unsigned)(~i);
            }
        }
        __syncthreads();

        // bitonic sort 512 descending, 4 keys/thread (thread t owns i = t*4+r)
        u64 v[4];
#pragma unroll
        for (int r = 0; r < 4; r++) v[r] = sbuf[PIDX((tid << 2) + r)];
        __syncthreads();

        auto intra = [&](int j, int k2) {
#pragma unroll
            for (int r = 0; r < 4; r++) {
                if (!(r & j)) {
                    int r2 = r | j;
                    bool dir = ((((tid << 2) + r) & k2) == 0);
                    u64 a = v[r], bq = v[r2];
                    if ((a < bq) == dir) { v[r] = bq; v[r2] = a; }
                }
            }
        };
        auto shfl = [&](int j, int k2) {
            int d = j >> 2;      // lane distance 1..16
            bool keepmax = (((tid & d) != 0) ^ (((tid << 2) & k2) == 0));
#pragma unroll
            for (int r = 0; r < 4; r++) {
                u64 o = __shfl_xor_sync(0xffffffffu, v[r], d);
                v[r] = keepmax ? (v[r] > o ? v[r] : o) : (v[r] < o ? v[r] : o);
            }
        };
        auto xshared = [&](int j, int k2) {
            int d = j >> 2;      // thread distance >= 32 -> cross-warp
#pragma unroll
            for (int r = 0; r < 4; r++) sbuf[PIDX((tid << 2) + r)] = v[r];
            __syncthreads();
            int p = tid ^ d;
            bool keepmax = (((tid & d) != 0) ^ (((tid << 2) & k2) == 0));
#pragma unroll
            for (int r = 0; r < 4; r++) {
                u64 o = sbuf[PIDX((p << 2) + r)];
                v[r] = keepmax ? (v[r] > o ? v[r] : o) : (v[r] < o ? v[r] : o);
            }
            __syncthreads();
        };

        for (int k2 = 2; k2 <= CAP; k2 <<= 1) {
            for (int j = k2 >> 1; j >= 128; j >>= 1) xshared(j, k2);
            int js = (k2 >> 1) < 64 ? (k2 >> 1) : 64;
            for (int j = js; j >= 4; j >>= 1) shfl(j, k2);
            int ji = (k2 >> 1) < 2 ? (k2 >> 1) : 2;
            for (int j = ji; j >= 1; j >>= 1) intra(j, k2);
        }

        // threads 0-63 hold sorted elements 0..255 -> park in smem
        if (tid < TOPM / 4) {
#pragma unroll
            for (int r = 0; r < 4; r++) tops[it][(tid << 2) + r] = v[r];
        }
        __syncthreads();
    }

    // ---- 4-warp parallel scan: warp w processes class bc0 + w ----
    {
        int bc = bc0 + wid;
        int b = bc / CC;
        const u64* top = tops[wid];
        float4* outb = g_selb + bc * K_OUT;
        float*  outs = g_sels + bc * K_OUT;
        const float4* boxes = g_boxes + b * NSEL;

        float ax1[4], ay1[4], ax2[4], ay2[4], aar[4];
        int nacc = 0;
        bool done = false;

        for (int base = 0; base < TOPM && !done; base += 32) {
            u64 key = top[base + lane];
            unsigned shi = (unsigned)(key >> 32);
            int idx = (int)(~(unsigned)key);
            float4 cb = make_float4(0.f, 0.f, 0.f, 0.f);
            if (shi > S03) cb = boxes[idx];

            for (int t = 0; t < 32; t++) {
                unsigned tshi = __shfl_sync(0xffffffffu, shi, t);
                if (tshi <= S03) { done = true; break; }
                float cx1 = __shfl_sync(0xffffffffu, cb.x, t);
                float cy1 = __shfl_sync(0xffffffffu, cb.y, t);
                float cx2 = __shfl_sync(0xffffffffu, cb.z, t);
                float cy2 = __shfl_sync(0xffffffffu, cb.w, t);
                float car = fmaxf(cx2 - cx1, 0.f) * fmaxf(cy2 - cy1, 0.f);
                bool sup = false;
#pragma unroll
                for (int s = 0; s < 4; s++) {
                    if ((s << 5) + lane < nacc) {
                        float xx1 = fmaxf(ax1[s], cx1), yy1 = fmaxf(ay1[s], cy1);
                        float xx2 = fminf(ax2[s], cx2), yy2 = fminf(ay2[s], cy2);
                        float inter = fmaxf(xx2 - xx1, 0.f) * fmaxf(yy2 - yy1, 0.f);
                        float iou = inter / fmaxf(aar[s] + car - inter, 1e-9f);
                        sup |= (iou > IOU_THR);
                    }
                }
                if (__ballot_sync(0xffffffffu, sup) == 0u) {
                    int sl = nacc >> 5, ln = nacc & 31;
#pragma unroll
                    for (int s = 0; s < 4; s++) {
                        if (s == sl && lane == ln) {
                            ax1[s] = cx1; ay1[s] = cy1; ax2[s] = cx2; ay2[s] = cy2;
                            aar[s] = car;
                        }
                    }
                    if (lane == 0) {
                        outb[nacc] = make_float4(cx1, cy1, cx2, cy2);
                        outs[nacc] = __uint_as_float(tshi & 0x7FFFFFFFu);
                    }
                    nacc++;
                    if (nacc == K_OUT) { done = true; break; }
                }
            }
        }
        // later selections would all be <=0.3 -> zeroed by keep mask anyway
        for (int kk = nacc + lane; kk < K_OUT; kk += 32) outs[kk] = -INFINITY;
    }
}

// ------------------------- K5: radix-select top-100 + small sort ------------
__global__ void __launch_bounds__(256) k_final(float* __restrict__ out) {
    int b = blockIdx.x;
    int tid = threadIdx.x, lane = tid & 31, wid = tid >> 5;

    unsigned key[32];
    const float* src = g_sels + (size_t)b * CC * K_OUT;
#pragma unroll
    for (int r = 0; r < 32; r++) {
        int f = tid + (r << 8);
        unsigned u = 0;
        if (f < CC * K_OUT) {
            u = f2sort(src[f]);
            if (u <= S03) u = 0;     // invalid for output -> excluded
        }
        key[r] = u;
    }

    __shared__ int s_w[2][8];
    __shared__ int s_cnt;
    __shared__ u64 sbuf[FCAP];

    unsigned ans = 0;
    int cur = CC * K_OUT;
    for (int bit = 31; bit >= 0; --bit) {
        if (cur <= FCAP) break;
        unsigned cand = ans | (1u << bit);
        int lc = 0;
#pragma unroll
        for (int r = 0; r < 32; r++) lc += (key[r] >= cand);
        lc = __reduce_add_sync(0xffffffffu, lc);
        if (lane == 0) s_w[bit & 1][wid] = lc;
        __syncthreads();
        int tot = 0;
#pragma unroll
        for (int w = 0; w < 8; w++) tot += s_w[bit & 1][w];
        if (tot >= K_OUT) { ans = cand; cur = tot; }
    }

    if (tid == 0) s_cnt = 0;
    for (int i = tid; i < FCAP; i += 256) sbuf[i] = 0ULL;
    __syncthreads();
#pragma unroll
    for (int r = 0; r < 32; r++) {
        bool pred = key[r] && (key[r] >= ans);
        unsigned m = __ballot_sync(0xffffffffu, pred);
        int cnt = __popc(m);
        int base = 0;
        if (lane == 0 && cnt) base = atomicAdd(&s_cnt, cnt);
        base = __shfl_sync(0xffffffffu, base, 0);
        if (pred) {
            int pos = base + __popc(m & ((1u << lane) - 1u));
            int f = tid + (r << 8);
            if (pos < FCAP) sbuf[pos] = ((u64)key[r] << 32) | (unsigned)(~f);
        }
    }
    __syncthreads();

    // warp 0: bitonic sort 256 descending, 8 keys/lane (i = lane*8 + r)
    if (wid == 0) {
        u64 v[8];
#pragma unroll
        for (int r = 0; r < 8; r++) v[r] = sbuf[(lane << 3) + r];

        auto intra8 = [&](int j, int k2) {
#pragma unroll
            for (int r = 0; r < 8; r++) {
                if (!(r & j)) {
                    int r2 = r | j;
                    bool dir = ((((lane << 3) + r) & k2) == 0);
                    u64 a = v[r], bq = v[r2];
                    if ((a < bq) == dir) { v[r] = bq; v[r2] = a; }
                }
            }
        };
        auto shfl8 = [&](int j, int k2) {
            int d = j >> 3;
            bool keepmax = (((lane & d) != 0) ^ (((lane << 3) & k2) == 0));
#pragma unroll
            for (int r = 0; r < 8; r++) {
                u64 o = __shfl_xor_sync(0xffffffffu, v[r], d);
                v[r] = keepmax ? (v[r] > o ? v[r] : o) : (v[r] < o ? v[r] : o);
            }
        };
        for (int k2 = 2; k2 <= 8; k2 <<= 1)
            for (int j = k2 >> 1; j >= 1; j >>= 1) intra8(j, k2);
        for (int k2 = 16; k2 <= 256; k2 <<= 1) {
            for (int j = k2 >> 1; j >= 8; j >>= 1) shfl8(j, k2);
            for (int j = 4; j >= 1; j >>= 1) intra8(j, k2);
        }
#pragma unroll
        for (int r = 0; r < 8; r++) sbuf[(lane << 3) + r] = v[r];
    }
    __syncthreads();

    for (int k = tid; k < K_OUT; k += 256) {
        u64 kk = sbuf[k];
        unsigned shi = (unsigned)(kk >> 32);
        float* o = out + ((size_t)b * K_OUT + k) * 6;
        if (shi > S03) {
            int f = (int)(~(unsigned)kk);
            float4 bb = g_selb[b * CC * K_OUT + f];
            o[0] = bb.x; o[1] = bb.y; o[2] = bb.z; o[3] = bb.w;
            o[4] = __uint_as_float(shi & 0x7FFFFFFFu);
            o[5] = (float)(f / K_OUT);
        } else {
            o[0] = 0.f; o[1] = 0.f; o[2] = 0.f; o[3] = 0.f; o[4] = 0.f; o[5] = 0.f;
        }
    }
}

// ------------------------- launch -------------------------------------------
extern "C" void kernel_launch(void* const* d_in, const int* in_sizes, int n_in,
                              void* d_out, int out_size) {
    const float *c0 = nullptr, *c1 = nullptr, *c2 = nullptr;
    const float *p0 = nullptr, *p1 = nullptr, *p2 = nullptr;
    for (int i = 0; i < n_in; i++) {
        const float* p = (const float*)d_in[i];
        switch (in_sizes[i]) {
            case BB * N0 * CC: c0 = p; break;
            case BB * N1 * CC: c1 = p; break;
            case BB * N2 * CC: c2 = p; break;
            case BB * N0 * 32: p0 = p; break;
            case BB * N1 * 32: p1 = p; break;
            case BB * N2 * 32: p2 = p; break;
            default: break;                   // origin_shapes (16) unused
        }
    }
    float* out = (float*)d_out;

    k_ml<<<MLGRID, 512>>>(c0, c1, c2);

    k_select<<<BB * 3, 1024>>>();

    int ntiles = (NSEL + TTILE - 1) / TTILE;
    k_decode<<<BB * ntiles, 256>>>(c0, c1, c2, p0, p1, p2);

    k_nms<<<BB * CC / 4, 128>>>();

    k_final<<<BB, 256>>>(out);
}

// round 13
// speedup vs baseline: 1.1184x; 1.1184x over previous
#include <cuda_runtime.h>
#include <math.h>
#include <stdint.h>

#define BB 8
#define CC 80
#define K_OUT 100
#define SEL 1000
#define NSEL 3000          // 3 levels x 1000 (level2 has 1024 > NMS_PRE=1000)
#define TOPM 256           // scan depth (scan consumes ~110; >2x margin)
#define CAP 512            // superset capacity for nms_sort
#define FCAP 256           // superset capacity for k_final
#define N0 16384
#define N1 4096
#define N2 1024
#define NTOT (N0 + N1 + N2)   // 21504
#define W0 128
#define W1 64
#define W2 32
#define IOU_THR 0.5f
#define BOX_SCORE 0.3f
#define IMGSZ 1024.0f
#define S03 0xBE99999Au    // sortable-uint encoding of 0.3f
#define PIDX(i) ((i) + ((i) >> 4))   // bank-conflict padding
#define MLR 128            // rows per k_ml tile
#define MLTILES (BB * NTOT / MLR)    // 1344
#define MLGRID 448                   // resident blocks (3 tiles each)

typedef unsigned long long u64;

// ------------------------- device scratch (no allocs allowed) ---------------
__device__ float  g_ml[BB * NTOT];            // max class logit per anchor
__device__ int    g_idx[BB * NSEL];           // selected anchor (level-local id)
__device__ float4 g_boxes[BB * NSEL];         // x1,y1,x2,y2
__device__ float  g_scores[BB * CC * NSEL];   // class-major sigmoid scores
__device__ u64    g_top[BB * CC * TOPM];      // per-(b,c) sorted top-256 keys
__device__ float4 g_selb[BB * CC * K_OUT];    // NMS-selected boxes
__device__ float  g_sels[BB * CC * K_OUT];    // NMS-selected scores

__device__ __forceinline__ unsigned f2sort(float x) {
    unsigned u = __float_as_uint(x);
    return (u & 0x80000000u) ? ~u : (u | 0x80000000u);
}

// ------------------------- K1: max class logit, persistent grid-stride ------
__global__ void __launch_bounds__(512) k_ml(const float* __restrict__ c0,
                                            const float* __restrict__ c1,
                                            const float* __restrict__ c2) {
    __shared__ float pm[MLR * 20];   // 2560 per-float4 maxes
    int tid = threadIdx.x;
    for (int t = blockIdx.x; t < MLTILES; t += MLGRID) {
        const float4* src;
        int R0, shift, mask, off;
        if (t < BB * N0 / MLR) {
            src = (const float4*)c0; R0 = t * MLR;
            shift = 14; mask = N0 - 1; off = 0;
        } else if (t < BB * (N0 + N1) / MLR) {
            src = (const float4*)c1; R0 = (t - BB * N0 / MLR) * MLR;
            shift = 12; mask = N1 - 1; off = N0;
        } else {
            src = (const float4*)c2; R0 = (t - BB * (N0 + N1) / MLR) * MLR;
            shift = 10; mask = N2 - 1; off = N0 + N1;
        }
        src += (size_t)R0 * 20;
#pragma unroll
        for (int p = 0; p < 5; p++) {
            int f = tid + (p << 9);      // 0..2559
            float4 v = src[f];
            pm[f] = fmaxf(fmaxf(v.x, v.y), fmaxf(v.z, v.w));
        }
        __syncthreads();
        if (tid < MLR) {
            float m = -INFINITY;
#pragma unroll
            for (int j = 0; j < 20; j++) m = fmaxf(m, pm[tid * 20 + j]);
            int R = R0 + tid;
            g_ml[(R >> shift) * NTOT + off + (R & mask)] = m;
        }
        __syncthreads();
    }
}

// ------------------------- K2: exact top-1000 per (image, level) ------------
__global__ void k_select() {
    int blk = blockIdx.x;
    int b = blk / 3, lvl = blk % 3;
    int N, off;
    if (lvl == 0)      { N = N0; off = 0; }
    else if (lvl == 1) { N = N1; off = N0; }
    else               { N = N2; off = N0 + N1; }
    int nwords = N >> 10;   // 16 / 4 / 1 per thread (1024 threads)

    int tid = threadIdx.x;
    int wid = tid >> 5, lane = tid & 31;
    const float* src = g_ml + b * NTOT + off;
    unsigned key[16];
    for (int r = 0; r < nwords; r++) key[r] = f2sort(src[tid + (r << 10)]);

    __shared__ int s_w[2][32];
    unsigned ans = 0;
    int tot = 0;
    for (int bit = 31; bit >= 0; --bit) {
        unsigned cand = ans | (1u << bit);
        int lc = 0;
        for (int r = 0; r < nwords; r++) lc += (key[r] >= cand);
        lc = __reduce_add_sync(0xffffffffu, lc);
        if (lane == 0) s_w[bit & 1][wid] = lc;
        __syncthreads();
        tot = __reduce_add_sync(0xffffffffu, s_w[bit & 1][lane]);
        if (tot >= SEL) {
            ans = cand;
            if (tot == SEL) break;   // exact set determined (uniform decision)
        }
    }
    {
        int lc = 0;
        for (int r = 0; r < nwords; r++) lc += (key[r] > ans);
        lc = __reduce_add_sync(0xffffffffu, lc);
        if (lane == 0) s_w[0][wid] = lc;
        __syncthreads();
        tot = __reduce_add_sync(0xffffffffu, s_w[0][lane]);
    }
    int cntG = tot;

    __shared__ int gp, ep;
    if (tid == 0) { gp = 0; ep = 0; }
    __syncthreads();
    int* out = g_idx + b * NSEL + lvl * SEL;
    for (int r = 0; r < nwords; r++) {
        unsigned u = key[r];
        int i = tid + (r << 10);
        if (u > ans)       { int p = atomicAdd(&gp, 1); out[p] = i; }
        else if (u == ans) { int e = atomicAdd(&ep, 1); int p = cntG + e; if (p < SEL) out[p] = i; }
    }
}

// ------------------------- K3: fused decode (boxes + transposed scores) -----
__device__ __forceinline__ void anchor_of(int b, int n, int& lvl, int& a) {
    a = g_idx[b * NSEL + n];
    lvl = (n < SEL) ? 0 : (n < 2 * SEL ? 1 : 2);
}

#define TTILE 32
__global__ void k_decode(const float* __restrict__ c0,
                         const float* __restrict__ c1,
                         const float* __restrict__ c2,
                         const float* __restrict__ p0,
                         const float* __restrict__ p1,
                         const float* __restrict__ p2) {
    __shared__ float tile[TTILE][CC + 1];
    __shared__ float sd[4][TTILE];    // DFL distances [side][anchor]
    int blk = blockIdx.x;
    int ntiles = (NSEL + TTILE - 1) / TTILE;
    int b = blk / ntiles;
    int base = (blk % ntiles) * TTILE;
    int tid = threadIdx.x;

    // threads 0-127: DFL distance (anchor = tid&31, side = tid>>5)
    if (tid < 128) {
        int al = tid & 31, s = tid >> 5;
        int n = base + al;
        if (n < NSEL) {
            int lvl, a;
            anchor_of(b, n, lvl, a);
            const float* bp; int NL; float stride;
            if (lvl == 0)      { bp = p0; NL = N0; stride = 8.f; }
            else if (lvl == 1) { bp = p1; NL = N1; stride = 16.f; }
            else               { bp = p2; NL = N2; stride = 32.f; }
            const float4* row4 = reinterpret_cast<const float4*>(bp + ((size_t)b * NL + a) * 32);
            float4 q0 = row4[s * 2], q1 = row4[s * 2 + 1];
            float v[8] = {q0.x, q0.y, q0.z, q0.w, q1.x, q1.y, q1.z, q1.w};
            float m = -INFINITY;
#pragma unroll
            for (int j = 0; j < 8; j++) m = fmaxf(m, v[j]);
            float se = 0.f, sw = 0.f;
#pragma unroll
            for (int j = 0; j < 8; j++) { float e = expf(v[j] - m); se += e; sw += e * (float)j; }
            sd[s][al] = sw / se * stride;
        }
    }

    // all threads: gather 32x80 score tile (coalesced rows)
    for (int idx = tid; idx < TTILE * CC; idx += blockDim.x) {
        int nl = idx / CC, c = idx % CC;
        int n = base + nl;
        float x = 0.f;
        if (n < NSEL) {
            int lvl, a;
            anchor_of(b, n, lvl, a);
            const float* cls; int NL;
            if (lvl == 0)      { cls = c0; NL = N0; }
            else if (lvl == 1) { cls = c1; NL = N1; }
            else               { cls = c2; NL = N2; }
            x = cls[((size_t)b * NL + a) * CC + c];
        }
        tile[nl][c] = 1.f / (1.f + expf(-x));
    }
    __syncthreads();

    // warp 0: assemble + clip boxes
    if (tid < 32) {
        int n = base + tid;
        if (n < NSEL) {
            int lvl, a;
            anchor_of(b, n, lvl, a);
            int Wd; float stride;
            if (lvl == 0)      { Wd = W0; stride = 8.f; }
            else if (lvl == 1) { Wd = W1; stride = 16.f; }
            else               { Wd = W2; stride = 32.f; }
            int h = a / Wd, w = a % Wd;
            float py = (h + 0.5f) * stride, px = (w + 0.5f) * stride;
            float y1 = fminf(fmaxf(py - sd[0][tid], 0.f), IMGSZ);
            float x1 = fminf(fmaxf(px - sd[1][tid], 0.f), IMGSZ);
            float y2 = fminf(fmaxf(py + sd[2][tid], 0.f), IMGSZ);
            float x2 = fminf(fmaxf(px + sd[3][tid], 0.f), IMGSZ);
            g_boxes[b * NSEL + n] = make_float4(x1, y1, x2, y2);
        }
    }

    // transpose-store scores (coalesced class-major)
    for (int idx = tid; idx < TTILE * CC; idx += blockDim.x) {
        int c = idx / TTILE, nl = idx % TTILE;
        int n = base + nl;
        if (n < NSEL)
            g_scores[((size_t)b * CC + c) * NSEL + n] = tile[nl][c];
    }
}

// ------------------------- K4a: windowed radix select + 512-sort, 128 thr ---
__global__ void __launch_bounds__(128) k_nms_sort() {
    int bc = blockIdx.x;
    int tid = threadIdx.x;
    int lane = tid & 31, wid = tid >> 5;

    // 24 keys via 6 float4 loads (750 float4 over 128 threads)
    unsigned key[24];
    const float4* sc4 = reinterpret_cast<const float4*>(g_scores + (size_t)bc * NSEL);
#pragma unroll
    for (int p = 0; p < 6; p++) {
        int q = tid + (p << 7);
        if (q < NSEL / 4) {
            float4 f = sc4[q];
            key[p * 4 + 0] = f2sort(f.x);
            key[p * 4 + 1] = f2sort(f.y);
            key[p * 4 + 2] = f2sort(f.z);
            key[p * 4 + 3] = f2sort(f.w);
        } else {
            key[p * 4 + 0] = key[p * 4 + 1] = key[p * 4 + 2] = key[p * 4 + 3] = 0u;
        }
    }

    __shared__ int s_w[2][4];
    __shared__ int s_cnt;
    __shared__ u64 sbuf[CAP + CAP / 16];

    // windowed radix search: stop once count(>=ans) in [TOPM, CAP]
    unsigned ans = 0;
    int cur = NSEL;
    for (int bit = 31; bit >= 0; --bit) {
        if (cur <= CAP) break;               // uniform decision
        unsigned cand = ans | (1u << bit);
        int lc = 0;
#pragma unroll
        for (int r = 0; r < 24; r++) lc += (key[r] >= cand);
        lc = __reduce_add_sync(0xffffffffu, lc);
        if (lane == 0) s_w[bit & 1][wid] = lc;
        __syncthreads();
        int tot = s_w[bit & 1][0] + s_w[bit & 1][1] + s_w[bit & 1][2] + s_w[bit & 1][3];
        if (tot >= TOPM) { ans = cand; cur = tot; }
    }

    // warp-aggregated compaction (order irrelevant: sort uses full key)
    if (tid == 0) s_cnt = 0;
    for (int i = tid; i < CAP + CAP / 16; i += 128) sbuf[i] = 0ULL;
    __syncthreads();
#pragma unroll
    for (int r = 0; r < 24; r++) {
        bool pred = (key[r] >= ans) && key[r];
        unsigned m = __ballot_sync(0xffffffffu, pred);
        int cnt = __popc(m);
        int base = 0;
        if (lane == 0 && cnt) base = atomicAdd(&s_cnt, cnt);
        base = __shfl_sync(0xffffffffu, base, 0);
        if (pred) {
            int pos = base + __popc(m & ((1u << lane) - 1u));
            int i = (tid + ((r >> 2) << 7)) * 4 + (r & 3);
            if (pos < CAP) sbuf[PIDX(pos)] = ((u64)key[r] << 32) | (unsigned)(~i);
        }
    }
    __syncthreads();

    // bitonic sort 512 descending, 4 keys/thread (thread t owns i = t*4 + r)
    u64 v[4];
#pragma unroll
    for (int r = 0; r < 4; r++) v[r] = sbuf[PIDX((tid << 2) + r)];
    __syncthreads();

    auto intra = [&](int j, int k2) {
#pragma unroll
        for (int r = 0; r < 4; r++) {
            if (!(r & j)) {
                int r2 = r | j;
                bool dir = ((((tid << 2) + r) & k2) == 0);
                u64 a = v[r], bq = v[r2];
                if ((a < bq) == dir) { v[r] = bq; v[r2] = a; }
            }
        }
    };
    auto shfl = [&](int j, int k2) {
        int d = j >> 2;      // lane distance 1..16
        bool keepmax = (((tid & d) != 0) ^ (((tid << 2) & k2) == 0));
#pragma unroll
        for (int r = 0; r < 4; r++) {
            u64 o = __shfl_xor_sync(0xffffffffu, v[r], d);
            v[r] = keepmax ? (v[r] > o ? v[r] : o) : (v[r] < o ? v[r] : o);
        }
    };
    auto xshared = [&](int j, int k2) {
        int d = j >> 2;      // thread distance >= 32 -> cross-warp
#pragma unroll
        for (int r = 0; r < 4; r++) sbuf[PIDX((tid << 2) + r)] = v[r];
        __syncthreads();
        int p = tid ^ d;
        bool keepmax = (((tid & d) != 0) ^ (((tid << 2) & k2) == 0));
#pragma unroll
        for (int r = 0; r < 4; r++) {
            u64 o = sbuf[PIDX((p << 2) + r)];
            v[r] = keepmax ? (v[r] > o ? v[r] : o) : (v[r] < o ? v[r] : o);
        }
        __syncthreads();
    };

    for (int k2 = 2; k2 <= CAP; k2 <<= 1) {
        for (int j = k2 >> 1; j >= 128; j >>= 1) xshared(j, k2);
        int js = (k2 >> 1) < 64 ? (k2 >> 1) : 64;
        for (int j = js; j >= 4; j >>= 1) shfl(j, k2);
        int ji = (k2 >> 1) < 2 ? (k2 >> 1) : 2;
        for (int j = ji; j >= 1; j >>= 1) intra(j, k2);
    }

    // threads 0-63 hold sorted elements 0..255 (exact top-256 prefix)
    if (tid < TOPM / 4) {
        u64* dst = g_top + (size_t)bc * TOPM + (tid << 2);
#pragma unroll
        for (int r = 0; r < 4; r++) dst[r] = v[r];
    }
}

// ------------------------- K4b: dense sorted-scan (warp per (b,c)) ----------
__global__ void k_nms_scan() {
    int warp = (blockIdx.x * blockDim.x + threadIdx.x) >> 5;
    int lane = threadIdx.x & 31;
    if (warp >= BB * CC) return;
    int b = warp / CC;

    const u64* top = g_top + (size_t)warp * TOPM;
    float4* outb = g_selb + warp * K_OUT;
    float*  outs = g_sels + warp * K_OUT;
    const float4* boxes = g_boxes + b * NSEL;

    float ax1[4], ay1[4], ax2[4], ay2[4], aar[4];
    int nacc = 0;
    bool done = false;

    for (int base = 0; base < TOPM && !done; base += 32) {
        u64 key = top[base + lane];
        unsigned shi = (unsigned)(key >> 32);
        int idx = (int)(~(unsigned)key);
        float4 cb = make_float4(0.f, 0.f, 0.f, 0.f);
        if (shi > S03) cb = boxes[idx];

        for (int t = 0; t < 32; t++) {
            unsigned tshi = __shfl_sync(0xffffffffu, shi, t);
            if (tshi <= S03) { done = true; break; }
            float cx1 = __shfl_sync(0xffffffffu, cb.x, t);
            float cy1 = __shfl_sync(0xffffffffu, cb.y, t);
            float cx2 = __shfl_sync(0xffffffffu, cb.z, t);
            float cy2 = __shfl_sync(0xffffffffu, cb.w, t);
            float car = fmaxf(cx2 - cx1, 0.f) * fmaxf(cy2 - cy1, 0.f);
            bool sup = false;
#pragma unroll
            for (int s = 0; s < 4; s++) {
                if ((s << 5) + lane < nacc) {
                    float xx1 = fmaxf(ax1[s], cx1), yy1 = fmaxf(ay1[s], cy1);
                    float xx2 = fminf(ax2[s], cx2), yy2 = fminf(ay2[s], cy2);
                    float inter = fmaxf(xx2 - xx1, 0.f) * fmaxf(yy2 - yy1, 0.f);
                    float iou = inter / fmaxf(aar[s] + car - inter, 1e-9f);
                    sup |= (iou > IOU_THR);
                }
            }
            if (__ballot_sync(0xffffffffu, sup) == 0u) {
                int sl = nacc >> 5, ln = nacc & 31;
#pragma unroll
                for (int s = 0; s < 4; s++) {
                    if (s == sl && lane == ln) {
                        ax1[s] = cx1; ay1[s] = cy1; ax2[s] = cx2; ay2[s] = cy2;
                        aar[s] = car;
                    }
                }
                if (lane == 0) {
                    outb[nacc] = make_float4(cx1, cy1, cx2, cy2);
                    outs[nacc] = __uint_as_float(tshi & 0x7FFFFFFFu);
                }
                nacc++;
                if (nacc == K_OUT) { done = true; break; }
            }
        }
    }
    // later selections would all be <=0.3 -> zeroed by keep mask anyway
    for (int kk = nacc + lane; kk < K_OUT; kk += 32) outs[kk] = -INFINITY;
}

// ------------------------- K5: radix-select top-100 + small sort ------------
__global__ void __launch_bounds__(256) k_final(float* __restrict__ out) {
    int b = blockIdx.x;
    int tid = threadIdx.x, lane = tid & 31, wid = tid >> 5;

    unsigned key[32];
    const float* src = g_sels + (size_t)b * CC * K_OUT;
#pragma unroll
    for (int r = 0; r < 32; r++) {
        int f = tid + (r << 8);
        unsigned u = 0;
        if (f < CC * K_OUT) {
            u = f2sort(src[f]);
            if (u <= S03) u = 0;     // invalid for output -> excluded
        }
        key[r] = u;
    }

    __shared__ int s_w[2][8];
    __shared__ int s_cnt;
    __shared__ u64 sbuf[FCAP];

    unsigned ans = 0;
    int cur = CC * K_OUT;
    for (int bit = 31; bit >= 0; --bit) {
        if (cur <= FCAP) break;
        unsigned cand = ans | (1u << bit);
        int lc = 0;
#pragma unroll
        for (int r = 0; r < 32; r++) lc += (key[r] >= cand);
        lc = __reduce_add_sync(0xffffffffu, lc);
        if (lane == 0) s_w[bit & 1][wid] = lc;
        __syncthreads();
        int tot = 0;
#pragma unroll
        for (int w = 0; w < 8; w++) tot += s_w[bit & 1][w];
        if (tot >= K_OUT) { ans = cand; cur = tot; }
    }

    if (tid == 0) s_cnt = 0;
    for (int i = tid; i < FCAP; i += 256) sbuf[i] = 0ULL;
    __syncthreads();
#pragma unroll
    for (int r = 0; r < 32; r++) {
        bool pred = key[r] && (key[r] >= ans);
        unsigned m = __ballot_sync(0xffffffffu, pred);
        int cnt = __popc(m);
        int base = 0;
        if (lane == 0 && cnt) base = atomicAdd(&s_cnt, cnt);
        base = __shfl_sync(0xffffffffu, base, 0);
        if (pred) {
            int pos = base + __popc(m & ((1u << lane) - 1u));
            int f = tid + (r << 8);
            if (pos < FCAP) sbuf[pos] = ((u64)key[r] << 32) | (unsigned)(~f);
        }
    }
    __syncthreads();

    // warp 0: bitonic sort 256 descending, 8 keys/lane (i = lane*8 + r)
    if (wid == 0) {
        u64 v[8];
#pragma unroll
        for (int r = 0; r < 8; r++) v[r] = sbuf[(lane << 3) + r];

        auto intra8 = [&](int j, int k2) {
#pragma unroll
            for (int r = 0; r < 8; r++) {
                if (!(r & j)) {
                    int r2 = r | j;
                    bool dir = ((((lane << 3) + r) & k2) == 0);
                    u64 a = v[r], bq = v[r2];
                    if ((a < bq) == dir) { v[r] = bq; v[r2] = a; }
                }
            }
        };
        auto shfl8 = [&](int j, int k2) {
            int d = j >> 3;
            bool keepmax = (((lane & d) != 0) ^ (((lane << 3) & k2) == 0));
#pragma unroll
            for (int r = 0; r < 8; r++) {
                u64 o = __shfl_xor_sync(0xffffffffu, v[r], d);
                v[r] = keepmax ? (v[r] > o ? v[r] : o) : (v[r] < o ? v[r] : o);
            }
        };
        for (int k2 = 2; k2 <= 8; k2 <<= 1)
            for (int j = k2 >> 1; j >= 1; j >>= 1) intra8(j, k2);
        for (int k2 = 16; k2 <= 256; k2 <<= 1) {
            for (int j = k2 >> 1; j >= 8; j >>= 1) shfl8(j, k2);
            for (int j = 4; j >= 1; j >>= 1) intra8(j, k2);
        }
#pragma unroll
        for (int r = 0; r < 8; r++) sbuf[(lane << 3) + r] = v[r];
    }
    __syncthreads();

    for (int k = tid; k < K_OUT; k += 256) {
        u64 kk = sbuf[k];
        unsigned shi = (unsigned)(kk >> 32);
        float* o = out + ((size_t)b * K_OUT + k) * 6;
        if (shi > S03) {
            int f = (int)(~(unsigned)kk);
            float4 bb = g_selb[b * CC * K_OUT + f];
            o[0] = bb.x; o[1] = bb.y; o[2] = bb.z; o[3] = bb.w;
            o[4] = __uint_as_float(shi & 0x7FFFFFFFu);
            o[5] = (float)(f / K_OUT);
        } else {
            o[0] = 0.f; o[1] = 0.f; o[2] = 0.f; o[3] = 0.f; o[4] = 0.f; o[5] = 0.f;
        }
    }
}

// ------------------------- launch -------------------------------------------
extern "C" void kernel_launch(void* const* d_in, const int* in_sizes, int n_in,
                              void* d_out, int out_size) {
    const float *c0 = nullptr, *c1 = nullptr, *c2 = nullptr;
    const float *p0 = nullptr, *p1 = nullptr, *p2 = nullptr;
    for (int i = 0; i < n_in; i++) {
        const float* p = (const float*)d_in[i];
        switch (in_sizes[i]) {
            case BB * N0 * CC: c0 = p; break;
            case BB * N1 * CC: c1 = p; break;
            case BB * N2 * CC: c2 = p; break;
            case BB * N0 * 32: p0 = p; break;
            case BB * N1 * 32: p1 = p; break;
            case BB * N2 * 32: p2 = p; break;
            default: break;                   // origin_shapes (16) unused
        }
    }
    float* out = (float*)d_out;

    k_ml<<<MLGRID, 512>>>(c0, c1, c2);

    k_select<<<BB * 3, 1024>>>();

    int ntiles = (NSEL + TTILE - 1) / TTILE;
    k_decode<<<BB * ntiles, 256>>>(c0, c1, c2, p0, p1, p2);

    k_nms_sort<<<BB * CC, 128>>>();

    k_nms_scan<<<(BB * CC + 3) / 4, 128>>>();

    k_final<<<BB, 256>>>(out);
}

// round 14
// speedup vs baseline: 1.2124x; 1.0841x over previous
#include <cuda_runtime.h>
#include <math.h>
#include <stdint.h>

#define BB 8
#define CC 80
#define K_OUT 100
#define SEL 1000
#define NSEL 3000          // 3 levels x 1000 (level2 has 1024 > NMS_PRE=1000)
#define TOPM 256           // scan depth (output-verified: 512 and 256 identical)
#define FCAP 256           // superset capacity for k_final
#define N0 16384
#define N1 4096
#define N2 1024
#define NTOT (N0 + N1 + N2)   // 21504
#define W0 128
#define W1 64
#define W2 32
#define IOU_THR 0.5f
#define BOX_SCORE 0.3f
#define IMGSZ 1024.0f
#define S03 0xBE99999Au    // sortable-uint encoding of 0.3f
#define PIDX(i) ((i) + ((i) >> 4))   // bank-conflict padding
#define MLR 128            // rows per k_ml tile
#define MLTILES (BB * NTOT / MLR)    // 1344
#define MLGRID 448                   // resident blocks (3 tiles each)

typedef unsigned long long u64;

// ------------------------- device scratch (no allocs allowed) ---------------
__device__ float  g_ml[BB * NTOT];            // max class logit per anchor
__device__ int    g_idx[BB * NSEL];           // selected anchor (level-local id)
__device__ float4 g_boxes[BB * NSEL];         // x1,y1,x2,y2
__device__ float  g_scores[BB * CC * NSEL];   // class-major sigmoid scores
__device__ u64    g_top[BB * CC * TOPM];      // per-(b,c) sorted top-256 keys
__device__ float4 g_selb[BB * CC * K_OUT];    // NMS-selected boxes
__device__ float  g_sels[BB * CC * K_OUT];    // NMS-selected scores

__device__ __forceinline__ unsigned f2sort(float x) {
    unsigned u = __float_as_uint(x);
    return (u & 0x80000000u) ? ~u : (u | 0x80000000u);
}

// ------------------------- K1: max class logit, persistent grid-stride ------
__global__ void __launch_bounds__(512) k_ml(const float* __restrict__ c0,
                                            const float* __restrict__ c1,
                                            const float* __restrict__ c2) {
    __shared__ float pm[MLR * 20];   // 2560 per-float4 maxes
    int tid = threadIdx.x;
    for (int t = blockIdx.x; t < MLTILES; t += MLGRID) {
        const float4* src;
        int R0, shift, mask, off;
        if (t < BB * N0 / MLR) {
            src = (const float4*)c0; R0 = t * MLR;
            shift = 14; mask = N0 - 1; off = 0;
        } else if (t < BB * (N0 + N1) / MLR) {
            src = (const float4*)c1; R0 = (t - BB * N0 / MLR) * MLR;
            shift = 12; mask = N1 - 1; off = N0;
        } else {
            src = (const float4*)c2; R0 = (t - BB * (N0 + N1) / MLR) * MLR;
            shift = 10; mask = N2 - 1; off = N0 + N1;
        }
        src += (size_t)R0 * 20;
#pragma unroll
        for (int p = 0; p < 5; p++) {
            int f = tid + (p << 9);      // 0..2559
            float4 v = src[f];
            pm[f] = fmaxf(fmaxf(v.x, v.y), fmaxf(v.z, v.w));
        }
        __syncthreads();
        if (tid < MLR) {
            float m = -INFINITY;
#pragma unroll
            for (int j = 0; j < 20; j++) m = fmaxf(m, pm[tid * 20 + j]);
            int R = R0 + tid;
            g_ml[(R >> shift) * NTOT + off + (R & mask)] = m;
        }
        __syncthreads();
    }
}

// ------------------------- K2: exact top-1000 per (image, level) ------------
__global__ void k_select() {
    int blk = blockIdx.x;
    int b = blk / 3, lvl = blk % 3;
    int N, off;
    if (lvl == 0)      { N = N0; off = 0; }
    else if (lvl == 1) { N = N1; off = N0; }
    else               { N = N2; off = N0 + N1; }
    int nwords = N >> 10;   // 16 / 4 / 1 per thread (1024 threads)

    int tid = threadIdx.x;
    int wid = tid >> 5, lane = tid & 31;
    const float* src = g_ml + b * NTOT + off;
    unsigned key[16];
    for (int r = 0; r < nwords; r++) key[r] = f2sort(src[tid + (r << 10)]);

    __shared__ int s_w[2][32];
    unsigned ans = 0;
    int tot = 0;
    for (int bit = 31; bit >= 0; --bit) {
        unsigned cand = ans | (1u << bit);
        int lc = 0;
        for (int r = 0; r < nwords; r++) lc += (key[r] >= cand);
        lc = __reduce_add_sync(0xffffffffu, lc);
        if (lane == 0) s_w[bit & 1][wid] = lc;
        __syncthreads();
        tot = __reduce_add_sync(0xffffffffu, s_w[bit & 1][lane]);
        if (tot >= SEL) {
            ans = cand;
            if (tot == SEL) break;   // exact set determined (uniform decision)
        }
    }
    {
        int lc = 0;
        for (int r = 0; r < nwords; r++) lc += (key[r] > ans);
        lc = __reduce_add_sync(0xffffffffu, lc);
        if (lane == 0) s_w[0][wid] = lc;
        __syncthreads();
        tot = __reduce_add_sync(0xffffffffu, s_w[0][lane]);
    }
    int cntG = tot;

    __shared__ int gp, ep;
    if (tid == 0) { gp = 0; ep = 0; }
    __syncthreads();
    int* out = g_idx + b * NSEL + lvl * SEL;
    for (int r = 0; r < nwords; r++) {
        unsigned u = key[r];
        int i = tid + (r << 10);
        if (u > ans)       { int p = atomicAdd(&gp, 1); out[p] = i; }
        else if (u == ans) { int e = atomicAdd(&ep, 1); int p = cntG + e; if (p < SEL) out[p] = i; }
    }
}

// ------------------------- K3: fused decode (boxes + transposed scores) -----
#define TTILE 32
#define TS 85   // tile row stride (conflict-free both access patterns)
__global__ void __launch_bounds__(256) k_decode(const float* __restrict__ c0,
                                                const float* __restrict__ c1,
                                                const float* __restrict__ c2,
                                                const float* __restrict__ p0,
                                                const float* __restrict__ p1,
                                                const float* __restrict__ p2) {
    __shared__ float tile[TTILE][TS];
    __shared__ float sd[4][TTILE];            // DFL distances [side][anchor]
    __shared__ const float4* rowc[TTILE];     // cls row ptr (as float4)
    __shared__ const float4* rowb[TTILE];     // bp row ptr
    __shared__ int meta[TTILE];               // (lvl<<28)|a
    int blk = blockIdx.x;
    int ntiles = (NSEL + TTILE - 1) / TTILE;
    int b = blk / ntiles;
    int base = (blk % ntiles) * TTILE;
    int tid = threadIdx.x;

    // warp 0: per-anchor row pointer table (once)
    if (tid < 32) {
        int n = base + tid;
        const float* cls = c0; const float* bp = p0; int NL = N0;
        int a = 0, lvl = 0;
        if (n < NSEL) {
            a = g_idx[b * NSEL + n];
            lvl = (n < SEL) ? 0 : (n < 2 * SEL ? 1 : 2);
            if (lvl == 1)      { cls = c1; bp = p1; NL = N1; }
            else if (lvl == 2) { cls = c2; bp = p2; NL = N2; }
        }
        rowc[tid] = reinterpret_cast<const float4*>(cls + ((size_t)b * NL + a) * CC);
        rowb[tid] = reinterpret_cast<const float4*>(bp + ((size_t)b * NL + a) * 32);
        meta[tid] = (lvl << 28) | a;
    }
    __syncthreads();

    // threads 0-127: DFL distance (anchor = tid&31, side = tid>>5)
    if (tid < 128) {
        int al = tid & 31, s = tid >> 5;
        if (base + al < NSEL) {
            int lvl = meta[al] >> 28;
            float stride = (lvl == 0) ? 8.f : (lvl == 1 ? 16.f : 32.f);
            float4 q0 = rowb[al][s * 2], q1 = rowb[al][s * 2 + 1];
            float v[8] = {q0.x, q0.y, q0.z, q0.w, q1.x, q1.y, q1.z, q1.w};
            float m = -INFINITY;
#pragma unroll
            for (int j = 0; j < 8; j++) m = fmaxf(m, v[j]);
            float se = 0.f, sw = 0.f;
#pragma unroll
            for (int j = 0; j < 8; j++) { float e = __expf(v[j] - m); se += e; sw += e * (float)j; }
            sd[s][al] = sw / se * stride;
        }
    }

    // all threads: vectorized score gather + sigmoid into tile
    for (int idx = tid; idx < TTILE * 20; idx += 256) {
        int nl = idx / 20, p = idx % 20;
        float4 v = rowc[nl][p];
        float4 sv;
        sv.x = 1.f / (1.f + __expf(-v.x));
        sv.y = 1.f / (1.f + __expf(-v.y));
        sv.z = 1.f / (1.f + __expf(-v.z));
        sv.w = 1.f / (1.f + __expf(-v.w));
        int c = p * 4;
        tile[nl][c] = sv.x; tile[nl][c + 1] = sv.y;
        tile[nl][c + 2] = sv.z; tile[nl][c + 3] = sv.w;
    }
    __syncthreads();

    // warp 0: assemble + clip boxes
    if (tid < 32) {
        int n = base + tid;
        if (n < NSEL) {
            int a = meta[tid] & 0x0FFFFFFF, lvl = meta[tid] >> 28;
            int Wd; float stride;
            if (lvl == 0)      { Wd = W0; stride = 8.f; }
            else if (lvl == 1) { Wd = W1; stride = 16.f; }
            else               { Wd = W2; stride = 32.f; }
            int h = a / Wd, w = a % Wd;
            float py = (h + 0.5f) * stride, px = (w + 0.5f) * stride;
            float y1 = fminf(fmaxf(py - sd[0][tid], 0.f), IMGSZ);
            float x1 = fminf(fmaxf(px - sd[1][tid], 0.f), IMGSZ);
            float y2 = fminf(fmaxf(py + sd[2][tid], 0.f), IMGSZ);
            float x2 = fminf(fmaxf(px + sd[3][tid], 0.f), IMGSZ);
            g_boxes[b * NSEL + n] = make_float4(x1, y1, x2, y2);
        }
    }

    // transpose store: class-major, vectorized for full tiles
    if (base + TTILE <= NSEL) {
        for (int idx = tid; idx < CC * 8; idx += 256) {
            int c = idx >> 3, q = idx & 7;
            float4 o;
            o.x = tile[q * 4 + 0][c]; o.y = tile[q * 4 + 1][c];
            o.z = tile[q * 4 + 2][c]; o.w = tile[q * 4 + 3][c];
            float* dst = g_scores + ((size_t)(b * CC + c)) * NSEL + base;
            reinterpret_cast<float4*>(dst)[q] = o;
        }
    } else {
        for (int idx = tid; idx < TTILE * CC; idx += 256) {
            int c = idx / TTILE, nl = idx % TTILE;
            int n = base + nl;
            if (n < NSEL)
                g_scores[((size_t)(b * CC + c)) * NSEL + n] = tile[nl][c];
        }
    }
}

// ------------------------- K4a: exact radix top-256 + 256-sort --------------
__global__ void __launch_bounds__(128) k_nms_sort() {
    int bc = blockIdx.x;
    int tid = threadIdx.x;
    int lane = tid & 31, wid = tid >> 5;

    // 24 keys via 6 float4 loads (750 float4 over 128 threads)
    unsigned key[24];
    const float4* sc4 = reinterpret_cast<const float4*>(g_scores + (size_t)bc * NSEL);
#pragma unroll
    for (int p = 0; p < 6; p++) {
        int q = tid + (p << 7);
        if (q < NSEL / 4) {
            float4 f = sc4[q];
            key[p * 4 + 0] = f2sort(f.x);
            key[p * 4 + 1] = f2sort(f.y);
            key[p * 4 + 2] = f2sort(f.z);
            key[p * 4 + 3] = f2sort(f.w);
        } else {
            key[p * 4 + 0] = key[p * 4 + 1] = key[p * 4 + 2] = key[p * 4 + 3] = 0u;
        }
    }

    __shared__ int s_w[2][4];
    __shared__ int s_gp, s_ep;
    __shared__ u64 sbuf[TOPM + TOPM / 16];

    // exact radix search for the TOPM-th largest key
    unsigned ans = 0;
    for (int bit = 31; bit >= 0; --bit) {
        unsigned cand = ans | (1u << bit);
        int lc = 0;
#pragma unroll
        for (int r = 0; r < 24; r++) lc += (key[r] >= cand);
        lc = __reduce_add_sync(0xffffffffu, lc);
        if (lane == 0) s_w[bit & 1][wid] = lc;
        __syncthreads();
        int tot = s_w[bit & 1][0] + s_w[bit & 1][1] + s_w[bit & 1][2] + s_w[bit & 1][3];
        if (tot >= TOPM) {
            ans = cand;
            if (tot == TOPM) break;     // exact set (uniform decision)
        }
    }
    // strict-greater count (cntG < TOPM by search invariant)
    int cntG;
    {
        int lc = 0;
#pragma unroll
        for (int r = 0; r < 24; r++) lc += (key[r] > ans);
        lc = __reduce_add_sync(0xffffffffu, lc);
        if (lane == 0) s_w[0][wid] = lc;
        __syncthreads();
        cntG = s_w[0][0] + s_w[0][1] + s_w[0][2] + s_w[0][3];
    }

    // compact: >ans anywhere in [0,cntG), ==ans ties fill [cntG, TOPM)
    if (tid == 0) { s_gp = 0; s_ep = 0; }
    for (int i = tid; i < TOPM + TOPM / 16; i += 128) sbuf[i] = 0ULL;
    __syncthreads();
#pragma unroll
    for (int r = 0; r < 24; r++) {
        unsigned u = key[r];
        bool pg = (u > ans);
        bool pe = (u == ans);
        unsigned mg = __ballot_sync(0xffffffffu, pg);
        unsigned me = __ballot_sync(0xffffffffu, pe);
        int bg = 0, be = 0;
        if (lane == 0 && mg) bg = atomicAdd(&s_gp, __popc(mg));
        if (lane == 0 && me) be = atomicAdd(&s_ep, __popc(me));
        bg = __shfl_sync(0xffffffffu, bg, 0);
        be = __shfl_sync(0xffffffffu, be, 0);
        int i = (tid + ((r >> 2) << 7)) * 4 + (r & 3);
        u64 kv = ((u64)u << 32) | (unsigned)(~i);
        if (pg) {
            int pos = bg + __popc(mg & ((1u << lane) - 1u));
            sbuf[PIDX(pos)] = kv;
        } else if (pe) {
            int pos = cntG + be + __popc(me & ((1u << lane) - 1u));
            if (pos < TOPM) sbuf[PIDX(pos)] = kv;
        }
    }
    __syncthreads();

    // bitonic sort 256 descending, 2 keys/thread (thread t owns i = t*2 + r)
    u64 v[2];
    v[0] = sbuf[PIDX(tid << 1)];
    v[1] = sbuf[PIDX((tid << 1) | 1)];
    __syncthreads();

    auto intra = [&](int k2) {      // j == 1
        bool dir = (((tid << 1) & k2) == 0);
        if ((v[0] < v[1]) == dir) { u64 t = v[0]; v[0] = v[1]; v[1] = t; }
    };
    auto shfl = [&](int j, int k2) {
        int d = j >> 1;             // lane distance 1..16
        bool keepmax = (((tid & d) != 0) ^ (((tid << 1) & k2) == 0));
#pragma unroll
        for (int r = 0; r < 2; r++) {
            u64 o = __shfl_xor_sync(0xffffffffu, v[r], d);
            v[r] = keepmax ? (v[r] > o ? v[r] : o) : (v[r] < o ? v[r] : o);
        }
    };
    auto xshared = [&](int j, int k2) {
        int d = j >> 1;             // thread distance >= 32 -> cross-warp
        sbuf[PIDX(tid << 1)] = v[0];
        sbuf[PIDX((tid << 1) | 1)] = v[1];
        __syncthreads();
        int p = tid ^ d;
        bool keepmax = (((tid & d) != 0) ^ (((tid << 1) & k2) == 0));
#pragma unroll
        for (int r = 0; r < 2; r++) {
            u64 o = sbuf[PIDX((p << 1) + r)];
            v[r] = keepmax ? (v[r] > o ? v[r] : o) : (v[r] < o ? v[r] : o);
        }
        __syncthreads();
    };

    for (int k2 = 2; k2 <= TOPM; k2 <<= 1) {
        for (int j = k2 >> 1; j >= 64; j >>= 1) xshared(j, k2);
        int js = (k2 >> 1) < 32 ? (k2 >> 1) : 32;
        for (int j = js; j >= 2; j >>= 1) shfl(j, k2);
        intra(k2);
    }

    // every thread holds 2 sorted keys -> exact top-256 in order
    u64* dst = g_top + (size_t)bc * TOPM;
    dst[(tid << 1)] = v[0];
    dst[(tid << 1) | 1] = v[1];
}

// ------------------------- K4b: dense sorted-scan (warp per (b,c)) ----------
__global__ void k_nms_scan() {
    int warp = (blockIdx.x * blockDim.x + threadIdx.x) >> 5;
    int lane = threadIdx.x & 31;
    if (warp >= BB * CC) return;
    int b = warp / CC;

    const u64* top = g_top + (size_t)warp * TOPM;
    float4* outb = g_selb + warp * K_OUT;
    float*  outs = g_sels + warp * K_OUT;
    const float4* boxes = g_boxes + b * NSEL;

    float ax1[4], ay1[4], ax2[4], ay2[4], aar[4];
    int nacc = 0;
    bool done = false;

    for (int base = 0; base < TOPM && !done; base += 32) {
        u64 key = top[base + lane];
        unsigned shi = (unsigned)(key >> 32);
        int idx = (int)(~(unsigned)key);
        float4 cb = make_float4(0.f, 0.f, 0.f, 0.f);
        if (shi > S03) cb = boxes[idx];

        for (int t = 0; t < 32; t++) {
            unsigned tshi = __shfl_sync(0xffffffffu, shi, t);
            if (tshi <= S03) { done = true; break; }
            float cx1 = __shfl_sync(0xffffffffu, cb.x, t);
            float cy1 = __shfl_sync(0xffffffffu, cb.y, t);
            float cx2 = __shfl_sync(0xffffffffu, cb.z, t);
            float cy2 = __shfl_sync(0xffffffffu, cb.w, t);
            float car = fmaxf(cx2 - cx1, 0.f) * fmaxf(cy2 - cy1, 0.f);
            bool sup = false;
#pragma unroll
            for (int s = 0; s < 4; s++) {
                if ((s << 5) + lane < nacc) {
                    float xx1 = fmaxf(ax1[s], cx1), yy1 = fmaxf(ay1[s], cy1);
                    float xx2 = fminf(ax2[s], cx2), yy2 = fminf(ay2[s], cy2);
                    float inter = fmaxf(xx2 - xx1, 0.f) * fmaxf(yy2 - yy1, 0.f);
                    float iou = inter / fmaxf(aar[s] + car - inter, 1e-9f);
                    sup |= (iou > IOU_THR);
                }
            }
            if (__ballot_sync(0xffffffffu, sup) == 0u) {
                int sl = nacc >> 5, ln = nacc & 31;
#pragma unroll
                for (int s = 0; s < 4; s++) {
                    if (s == sl && lane == ln) {
                        ax1[s] = cx1; ay1[s] = cy1; ax2[s] = cx2; ay2[s] = cy2;
                        aar[s] = car;
                    }
                }
                if (lane == 0) {
                    outb[nacc] = make_float4(cx1, cy1, cx2, cy2);
                    outs[nacc] = __uint_as_float(tshi & 0x7FFFFFFFu);
                }
                nacc++;
                if (nacc == K_OUT) { done = true; break; }
            }
        }
    }
    // later selections would all be <=0.3 -> zeroed by keep mask anyway
    for (int kk = nacc + lane; kk < K_OUT; kk += 32) outs[kk] = -INFINITY;
}

// ------------------------- K5: radix-select top-100 + small sort ------------
__global__ void __launch_bounds__(256) k_final(float* __restrict__ out) {
    int b = blockIdx.x;
    int tid = threadIdx.x, lane = tid & 31, wid = tid >> 5;

    unsigned key[32];
    const float* src = g_sels + (size_t)b * CC * K_OUT;
#pragma unroll
    for (int r = 0; r < 32; r++) {
        int f = tid + (r << 8);
        unsigned u = 0;
        if (f < CC * K_OUT) {
            u = f2sort(src[f]);
            if (u <= S03) u = 0;     // invalid for output -> excluded
        }
        key[r] = u;
    }

    __shared__ int s_w[2][8];
    __shared__ int s_cnt;
    __shared__ u64 sbuf[FCAP];

    unsigned ans = 0;
    int cur = CC * K_OUT;
    for (int bit = 31; bit >= 0; --bit) {
        if (cur <= FCAP) break;
        unsigned cand = ans | (1u << bit);
        int lc = 0;
#pragma unroll
        for (int r = 0; r < 32; r++) lc += (key[r] >= cand);
        lc = __reduce_add_sync(0xffffffffu, lc);
        if (lane == 0) s_w[bit & 1][wid] = lc;
        __syncthreads();
        int tot = 0;
#pragma unroll
        for (int w = 0; w < 8; w++) tot += s_w[bit & 1][w];
        if (tot >= K_OUT) { ans = cand; cur = tot; }
    }

    if (tid == 0) s_cnt = 0;
    for (int i = tid; i < FCAP; i += 256) sbuf[i] = 0ULL;
    __syncthreads();
#pragma unroll
    for (int r = 0; r < 32; r++) {
        bool pred = key[r] && (key[r] >= ans);
        unsigned m = __ballot_sync(0xffffffffu, pred);
        int cnt = __popc(m);
        int base = 0;
        if (lane == 0 && cnt) base = atomicAdd(&s_cnt, cnt);
        base = __shfl_sync(0xffffffffu, base, 0);
        if (pred) {
            int pos = base + __popc(m & ((1u << lane) - 1u));
            int f = tid + (r << 8);
            if (pos < FCAP) sbuf[pos] = ((u64)key[r] << 32) | (unsigned)(~f);
        }
    }
    __syncthreads();

    // warp 0: bitonic sort 256 descending, 8 keys/lane (i = lane*8 + r)
    if (wid == 0) {
        u64 v[8];
#pragma unroll
        for (int r = 0; r < 8; r++) v[r] = sbuf[(lane << 3) + r];

        auto intra8 = [&](int j, int k2) {
#pragma unroll
            for (int r = 0; r < 8; r++) {
                if (!(r & j)) {
                    int r2 = r | j;
                    bool dir = ((((lane << 3) + r) & k2) == 0);
                    u64 a = v[r], bq = v[r2];
                    if ((a < bq) == dir) { v[r] = bq; v[r2] = a; }
                }
            }
        };
        auto shfl8 = [&](int j, int k2) {
            int d = j >> 3;
            bool keepmax = (((lane & d) != 0) ^ (((lane << 3) & k2) == 0));
#pragma unroll
            for (int r = 0; r < 8; r++) {
                u64 o = __shfl_xor_sync(0xffffffffu, v[r], d);
                v[r] = keepmax ? (v[r] > o ? v[r] : o) : (v[r] < o ? v[r] : o);
            }
        };
        for (int k2 = 2; k2 <= 8; k2 <<= 1)
            for (int j = k2 >> 1; j >= 1; j >>= 1) intra8(j, k2);
        for (int k2 = 16; k2 <= 256; k2 <<= 1) {
            for (int j = k2 >> 1; j >= 8; j >>= 1) shfl8(j, k2);
            for (int j = 4; j >= 1; j >>= 1) intra8(j, k2);
        }
#pragma unroll
        for (int r = 0; r < 8; r++) sbuf[(lane << 3) + r] = v[r];
    }
    __syncthreads();

    for (int k = tid; k < K_OUT; k += 256) {
        u64 kk = sbuf[k];
        unsigned shi = (unsigned)(kk >> 32);
        float* o = out + ((size_t)b * K_OUT + k) * 6;
        if (shi > S03) {
            int f = (int)(~(unsigned)kk);
            float4 bb = g_selb[b * CC * K_OUT + f];
            o[0] = bb.x; o[1] = bb.y; o[2] = bb.z; o[3] = bb.w;
            o[4] = __uint_as_float(shi & 0x7FFFFFFFu);
            o[5] = (float)(f / K_OUT);
        } else {
            o[0] = 0.f; o[1] = 0.f; o[2] = 0.f; o[3] = 0.f; o[4] = 0.f; o[5] = 0.f;
        }
    }
}

// ------------------------- launch -------------------------------------------
extern "C" void kernel_launch(void* const* d_in, const int* in_sizes, int n_in,
                              void* d_out, int out_size) {
    const float *c0 = nullptr, *c1 = nullptr, *c2 = nullptr;
    const float *p0 = nullptr, *p1 = nullptr, *p2 = nullptr;
    for (int i = 0; i < n_in; i++) {
        const float* p = (const float*)d_in[i];
        switch (in_sizes[i]) {
            case BB * N0 * CC: c0 = p; break;
            case BB * N1 * CC: c1 = p; break;
            case BB * N2 * CC: c2 = p; break;
            case BB * N0 * 32: p0 = p; break;
            case BB * N1 * 32: p1 = p; break;
            case BB * N2 * 32: p2 = p; break;
            default: break;                   // origin_shapes (16) unused
        }
    }
    float* out = (float*)d_out;

    k_ml<<<MLGRID, 512>>>(c0, c1, c2);

    k_select<<<BB * 3, 1024>>>();

    int ntiles = (NSEL + TTILE - 1) / TTILE;
    k_decode<<<BB * ntiles, 256>>>(c0, c1, c2, p0, p1, p2);

    k_nms_sort<<<BB * CC, 128>>>();

    k_nms_scan<<<(BB * CC + 3) / 4, 128>>>();

    k_final<<<BB, 256>>>(out);
}